// round 6
// baseline (speedup 1.0000x reference)
#include <cuda_runtime.h>
#include <cstdint>

#define BB 4
#define CC 256
#define HH 56
#define WW 56
#define CO 128
#define NT 49
#define HW 3136
#define GTOT 392          // 49 taps x 8 ci-blocks of 32
#define KSPL 3

typedef unsigned long long u64;

// ---- device-global scratch ----
__device__ __align__(16) float g_W1b[GTOT * 4096];        // tf32 weights [g][co][k]
__device__ __align__(16) float g_part[KSPL * BB * CO * HW]; // conv1 K-split partials
__device__ __align__(16) float g_attn[BB * NT * HW];      // softmax attention

// ---------- helpers ----------
__device__ __forceinline__ uint32_t smem_to_u32(const void* p) {
    uint32_t a;
    asm("{ .reg .u64 t; cvta.to.shared.u64 t, %1; cvt.u32.u64 %0, t; }" : "=r"(a) : "l"(p));
    return a;
}
__device__ __forceinline__ uint32_t cvt_tf32(float f) {
    uint32_t u;
    asm("cvt.rn.tf32.f32 %0, %1;" : "=r"(u) : "f"(f));
    return u;
}
#define CP16(dst, src) \
    asm volatile("cp.async.cg.shared.global [%0], [%1], 16;" :: "r"(dst), "l"(src) : "memory")
#define CP_COMMIT() asm volatile("cp.async.commit_group;" ::: "memory")
#define CP_WAIT0()  asm volatile("cp.async.wait_group 0;" ::: "memory")

#define MMA_TF32(d, a, bfr) \
    asm volatile("mma.sync.aligned.m16n8k8.row.col.f32.tf32.tf32.f32 " \
        "{%0,%1,%2,%3}, {%4,%5,%6,%7}, {%8,%9}, {%0,%1,%2,%3};" \
        : "+f"((d)[0]), "+f"((d)[1]), "+f"((d)[2]), "+f"((d)[3]) \
        : "r"((a)[0]), "r"((a)[1]), "r"((a)[2]), "r"((a)[3]), \
          "r"((bfr)[0]), "r"((bfr)[1]))

__device__ __forceinline__ void sts128(uint32_t a, uint32_t r0, uint32_t r1,
                                       uint32_t r2, uint32_t r3) {
    asm volatile("st.shared.v4.b32 [%0], {%1,%2,%3,%4};"
                 :: "r"(a), "r"(r0), "r"(r1), "r"(r2), "r"(r3) : "memory");
}
// ---------- f32x2 helpers for scalar kernels ----------
__device__ __forceinline__ void fma2(u64& d, u64 a, u64 b) {
    asm("fma.rn.f32x2 %0, %1, %2, %0;" : "+l"(d) : "l"(a), "l"(b));
}
__device__ __forceinline__ float2 unpack2(u64 v) {
    float2 f;
    asm("mov.b64 {%0, %1}, %2;" : "=f"(f.x), "=f"(f.y) : "l"(v));
    return f;
}
__device__ __forceinline__ u64 lds64(const float* p) {
    return *reinterpret_cast<const u64*>(p);
}

// =====================================================================
// Kernel 0: bake W1 -> g_W1b[g][co][k] as tf32 (cvt.rn).  g = tap*8+cib.
// =====================================================================
__global__ void __launch_bounds__(256) prep_w1(const float* __restrict__ W1)
{
    int idx = blockIdx.x * 256 + threadIdx.x;     // 392*4096
    int g = idx >> 12, e = idx & 4095;
    int co = e >> 5, k = e & 31;
    int tap = g >> 3, cib = g & 7;
    float wv = W1[((size_t)co * CC + cib * 32 + k) * NT + tap];
    g_W1b[idx] = __uint_as_float(cvt_tf32(wv));
}

// =====================================================================
// Kernel A: conv1 tf32 mma.sync GEMM. Grid (98, 3), 256 threads (8 warps).
// CTA: 128px x 128co over ~131 K-groups (K-split 3 across grid.y).
// Warps 0-3: k 0..15 of each group; warps 4-7: k 16..31. Epilogue sums.
// =====================================================================
#define ASTRIDE 36
#define ABYTES  (128 * ASTRIDE * 4)     // 18432
#define CONV1_SMEM (4 * ABYTES)         // 73728

__global__ void __launch_bounds__(256, 2) conv1_mma(const float* __restrict__ x)
{
    extern __shared__ __align__(16) char smem[];
    float* const As0 = (float*)smem;
    float* const Bs0 = (float*)(smem + 2 * ABYTES);

    const int tid = threadIdx.x;
    const int wid = tid >> 5, lane = tid & 31;
    const int g8 = lane >> 2, t4 = lane & 3;
    const int tile = wid & 3, khalf = wid >> 2;
    const int m0 = (tile >> 1) * 64, n0 = (tile & 1) * 64;

    const int q = blockIdx.y;
    const int gstart = q * 131;
    const int gend = (q == 2) ? GTOT : (gstart + 131);

    // A loading role: 2 threads per pixel row (16 k each)
    const int r = tid >> 1;
    const int kh16 = (tid & 1) * 16;
    const int px = blockIdx.x * 128 + r;
    const int b = px / HW, rem = px % HW;
    const int h = rem / WW, w0 = rem % WW;

    const uint32_t sb = smem_to_u32(smem);
    const uint32_t a_st_base = sb + (uint32_t)(r * ASTRIDE + kh16) * 4;
    const uint32_t b_cp_base = sb + 2 * (uint32_t)ABYTES;

    float acc[4][8][4];
#pragma unroll
    for (int i = 0; i < 4; ++i)
#pragma unroll
        for (int j = 0; j < 8; ++j)
#pragma unroll
            for (int c = 0; c < 4; ++c) acc[i][j][c] = 0.f;

    float v[16];

    auto lda = [&](int g) {
        int tap = g >> 3, cib = g & 7;
        int di = tap / 7, dj = tap - di * 7;
        int ir = h - 6 + 2 * di, ic = w0 - 6 + 2 * dj;
        bool ok = ((unsigned)ir < HH) && ((unsigned)ic < WW);
        const float* xb = x + ((size_t)(b * CC + cib * 32 + kh16)) * HW + ir * WW + ic;
#pragma unroll
        for (int k = 0; k < 16; ++k)
            v[k] = ok ? __ldg(xb + (size_t)k * HW) : 0.f;
    };
    auto ldb = [&](int g, int buf) {
        const char* src = (const char*)(g_W1b + (size_t)g * 4096);
        uint32_t dstb = b_cp_base + (uint32_t)buf * ABYTES;
#pragma unroll
        for (int i = 0; i < 4; ++i) {
            int c = tid + i * 256;            // float4 chunk 0..1023
            int co = c >> 3, kq = c & 7;
            uint32_t d = dstb + (uint32_t)(co * ASTRIDE + kq * 4) * 4;
            CP16(d, src + (size_t)c * 16);
        }
    };
    auto sta = [&](int buf) {
        uint32_t dst = a_st_base + (uint32_t)buf * ABYTES;
#pragma unroll
        for (int k = 0; k < 16; k += 4)
            sts128(dst + k * 4, cvt_tf32(v[k]), cvt_tf32(v[k + 1]),
                   cvt_tf32(v[k + 2]), cvt_tf32(v[k + 3]));
    };

    // prologue
    lda(gstart); ldb(gstart, 0); CP_COMMIT();
    sta(0);
    CP_WAIT0();
    __syncthreads();

    for (int g = gstart; g < gend; ++g) {
        const int cur = (g - gstart) & 1;
        if (g + 1 < gend) { lda(g + 1); ldb(g + 1, cur ^ 1); CP_COMMIT(); }

        const float* ap = As0 + (size_t)cur * (ABYTES / 4) + m0 * ASTRIDE;
        const float* bp = Bs0 + (size_t)cur * (ABYTES / 4) + n0 * ASTRIDE;
#pragma unroll
        for (int kk = 0; kk < 2; ++kk) {
            const int k0 = khalf * 16 + kk * 8;
            uint32_t af[4][4], bf[8][2];
#pragma unroll
            for (int i = 0; i < 4; ++i) {
                const float* ar = ap + (16 * i + g8) * ASTRIDE + k0 + t4;
                af[i][0] = __float_as_uint(ar[0]);
                af[i][1] = __float_as_uint(ar[8 * ASTRIDE]);
                af[i][2] = __float_as_uint(ar[4]);
                af[i][3] = __float_as_uint(ar[8 * ASTRIDE + 4]);
            }
#pragma unroll
            for (int j = 0; j < 8; ++j) {
                const float* br = bp + (8 * j + g8) * ASTRIDE + k0 + t4;
                bf[j][0] = __float_as_uint(br[0]);
                bf[j][1] = __float_as_uint(br[4]);
            }
#pragma unroll
            for (int i = 0; i < 4; ++i)
#pragma unroll
                for (int j = 0; j < 8; ++j)
                    MMA_TF32(acc[i][j], af[i], bf[j]);
        }

        if (g + 1 < gend) { sta(cur ^ 1); CP_WAIT0(); }
        __syncthreads();
    }

    // ---- epilogue: sum k-halves in smem (layout [co][px], stride 132) ----
    float* const Cs = (float*)smem;
    if (khalf == 0) {
#pragma unroll
        for (int i = 0; i < 4; ++i)
#pragma unroll
            for (int j = 0; j < 8; ++j) {
                int row0 = m0 + 16 * i + g8;
                int col0 = n0 + 8 * j + 2 * t4;
                Cs[(col0)     * 132 + row0]     = acc[i][j][0];
                Cs[(col0 + 1) * 132 + row0]     = acc[i][j][1];
                Cs[(col0)     * 132 + row0 + 8] = acc[i][j][2];
                Cs[(col0 + 1) * 132 + row0 + 8] = acc[i][j][3];
            }
    }
    __syncthreads();
    if (khalf == 1) {
#pragma unroll
        for (int i = 0; i < 4; ++i)
#pragma unroll
            for (int j = 0; j < 8; ++j) {
                int row0 = m0 + 16 * i + g8;
                int col0 = n0 + 8 * j + 2 * t4;
                Cs[(col0)     * 132 + row0]     += acc[i][j][0];
                Cs[(col0 + 1) * 132 + row0]     += acc[i][j][1];
                Cs[(col0)     * 132 + row0 + 8] += acc[i][j][2];
                Cs[(col0 + 1) * 132 + row0 + 8] += acc[i][j][3];
            }
    }
    __syncthreads();

    // ---- stream out to g_part[q] (coalesced over px) ----
    {
        const int pxl = tid & 127, ch = tid >> 7;
        const int pxg = blockIdx.x * 128 + pxl;
        const int b2 = pxg / HW, rem2 = pxg % HW;
        float* base = g_part + ((size_t)(q * BB + b2) * CO) * HW + rem2;
#pragma unroll 4
        for (int co = ch * 64; co < ch * 64 + 64; ++co)
            base[(size_t)co * HW] = Cs[co * 132 + pxl];
    }
}

// =====================================================================
// Kernel B: sum 3 K-split slices + b1, conv2 (1x1) + b2, softmax(49)
// =====================================================================
__global__ void __launch_bounds__(256) conv2_softmax_kernel(
    const float* __restrict__ W2, const float* __restrict__ b1,
    const float* __restrict__ b2)
{
    __shared__ float k1s[128][57];
    __shared__ float ls[49][57];
    const int h = blockIdx.x, b = blockIdx.y, tid = threadIdx.x;

    for (int t = tid; t < 128 * 56; t += 256) {
        int c = t / 56, p = t - c * 56;
        size_t base = (size_t)(b * CO + c) * HW + h * WW + p;
        float v = b1[c];
#pragma unroll
        for (int q = 0; q < KSPL; ++q)
            v += g_part[(size_t)q * BB * CO * HW + base];
        k1s[c][p] = v;
    }
    __syncthreads();

    for (int idx = tid; idx < 49 * 56; idx += 256) {
        int kk = idx / 56, p = idx - kk * 56;
        float acc = b2[kk];
        const float* wr = &W2[kk * 128];
#pragma unroll 8
        for (int c = 0; c < 128; ++c) acc += __ldg(&wr[c]) * k1s[c][p];
        ls[kk][p] = acc;
    }
    __syncthreads();

    if (tid < 56) {
        int p = tid;
        float m = -1e30f;
#pragma unroll
        for (int kk = 0; kk < 49; ++kk) m = fmaxf(m, ls[kk][p]);
        float s = 0.f;
#pragma unroll
        for (int kk = 0; kk < 49; ++kk) {
            float e = expf(ls[kk][p] - m);
            ls[kk][p] = e;
            s += e;
        }
        float inv = 1.f / s;
#pragma unroll
        for (int kk = 0; kk < 49; ++kk) ls[kk][p] *= inv;
    }
    __syncthreads();

    for (int t = tid; t < 49 * 56; t += 256) {
        int kk = t / 56, p = t - kk * 56;
        g_attn[((size_t)b * NT + kk) * HW + h * WW + p] = ls[kk][p];
    }
}

// =====================================================================
// Kernel C: weighted local sum over 49 dilated taps -> out
// Grid (56, 4, 2), 224 threads. 8-ch x-chunks for high occupancy.
// =====================================================================
__global__ void __launch_bounds__(224) gather_kernel(
    const float* __restrict__ x, float* __restrict__ out)
{
    __shared__ __align__(16) float at[49][58];
    __shared__ __align__(16) float xs[8][7][68];     // 15232B -> ~8 CTAs/SM
    const int h = blockIdx.x, b = blockIdx.y;
    const int chalf = blockIdx.z * 128;
    const int tid = threadIdx.x;

    for (int t = tid; t < 49 * 56; t += 224) {
        int kk = t / 56, p = t - kk * 56;
        at[kk][p] = g_attn[((size_t)b * NT + kk) * HW + h * WW + p];
    }

    const int pg = tid % 28, cg = tid / 28;   // 28 px-pairs x 8 channels
    const int p0 = pg * 2;

    for (int ch = 0; ch < 16; ++ch) {
        __syncthreads();
        for (int t = tid; t < 8 * 476; t += 224) {
            int c = t / 476, rr = t - c * 476;
            int i = rr / 68, col = rr - i * 68;
            int row = h - 6 + 2 * i, gcol = col - 6;
            float v = 0.f;
            if ((unsigned)row < HH && (unsigned)gcol < WW)
                v = x[((size_t)(b * CC + chalf + ch * 8 + c)) * HW + row * WW + gcol];
            xs[c][i][col] = v;
        }
        __syncthreads();

        u64 a0 = 0ull;
#pragma unroll
        for (int i = 0; i < 7; ++i) {
            const float* xrow = &xs[cg][i][p0];
#pragma unroll
            for (int j = 0; j < 7; ++j)
                fma2(a0, lds64(&at[i * 7 + j][p0]), lds64(xrow + 2 * j));
        }
        size_t o = (size_t)(b * CC + chalf + ch * 8 + cg) * HW + h * WW + p0;
        *reinterpret_cast<float2*>(&out[o]) = unpack2(a0);
    }
}

// =====================================================================
extern "C" void kernel_launch(void* const* d_in, const int* in_sizes, int n_in,
                              void* d_out, int out_size)
{
    const float* x  = (const float*)d_in[0];
    const float* W1 = (const float*)d_in[1];
    const float* b1 = (const float*)d_in[2];
    const float* W2 = (const float*)d_in[3];
    const float* b2 = (const float*)d_in[4];
    for (int i = 0; i < n_in; ++i) {
        switch (in_sizes[i]) {
            case BB * CC * HW: x  = (const float*)d_in[i]; break;
            case CO * CC * NT: W1 = (const float*)d_in[i]; break;
            case CO:           b1 = (const float*)d_in[i]; break;
            case NT * CO:      W2 = (const float*)d_in[i]; break;
            case NT:           b2 = (const float*)d_in[i]; break;
            default: break;
        }
    }
    float* out = (float*)d_out;

    cudaFuncSetAttribute(conv1_mma, cudaFuncAttributeMaxDynamicSharedMemorySize,
                         CONV1_SMEM);
    prep_w1<<<6272, 256>>>(W1);
    conv1_mma<<<dim3(98, KSPL), 256, CONV1_SMEM>>>(x);
    conv2_softmax_kernel<<<dim3(56, 4), 256>>>(W2, b1, b2);
    gather_kernel<<<dim3(56, 4, 2), 224>>>(x, out);
}

// round 7
// speedup vs baseline: 2.0524x; 2.0524x over previous
#include <cuda_runtime.h>
#include <cstdint>

#define BB 4
#define CC 256
#define HH 56
#define WW 56
#define CO 128
#define NT 49
#define HW 3136
#define GTOT 392          // 49 taps x 8 ci-blocks of 32
#define KSPL 3

typedef unsigned long long u64;

// ---- device-global scratch ----
__device__ __align__(16) float g_W1b[GTOT * 4096];          // tf32 weights [g][co][k]
__device__ __align__(16) float g_part[KSPL * BB * CO * HW]; // conv1 K-split partials
__device__ __align__(16) float g_attn[BB * NT * HW];        // softmax attention

// ---------- helpers ----------
__device__ __forceinline__ uint32_t smem_to_u32(const void* p) {
    uint32_t a;
    asm("{ .reg .u64 t; cvta.to.shared.u64 t, %1; cvt.u32.u64 %0, t; }" : "=r"(a) : "l"(p));
    return a;
}
__device__ __forceinline__ uint32_t cvt_tf32(float f) {
    uint32_t u;
    asm("cvt.rn.tf32.f32 %0, %1;" : "=r"(u) : "f"(f));
    return u;
}
#define CP16(dst, src) \
    asm volatile("cp.async.cg.shared.global [%0], [%1], 16;" :: "r"(dst), "l"(src) : "memory")
#define CP_COMMIT() asm volatile("cp.async.commit_group;" ::: "memory")
#define CP_WAIT0()  asm volatile("cp.async.wait_group 0;" ::: "memory")

#define MMA_TF32(d, a, bfr) \
    asm volatile("mma.sync.aligned.m16n8k8.row.col.f32.tf32.tf32.f32 " \
        "{%0,%1,%2,%3}, {%4,%5,%6,%7}, {%8,%9}, {%0,%1,%2,%3};" \
        : "+f"((d)[0]), "+f"((d)[1]), "+f"((d)[2]), "+f"((d)[3]) \
        : "r"((a)[0]), "r"((a)[1]), "r"((a)[2]), "r"((a)[3]), \
          "r"((bfr)[0]), "r"((bfr)[1]))

__device__ __forceinline__ void sts128(uint32_t a, uint32_t r0, uint32_t r1,
                                       uint32_t r2, uint32_t r3) {
    asm volatile("st.shared.v4.b32 [%0], {%1,%2,%3,%4};"
                 :: "r"(a), "r"(r0), "r"(r1), "r"(r2), "r"(r3) : "memory");
}
// ---------- f32x2 helpers for scalar kernels ----------
__device__ __forceinline__ void fma2(u64& d, u64 a, u64 b) {
    asm("fma.rn.f32x2 %0, %1, %2, %0;" : "+l"(d) : "l"(a), "l"(b));
}
__device__ __forceinline__ float2 unpack2(u64 v) {
    float2 f;
    asm("mov.b64 {%0, %1}, %2;" : "=f"(f.x), "=f"(f.y) : "l"(v));
    return f;
}
__device__ __forceinline__ u64 lds64(const float* p) {
    return *reinterpret_cast<const u64*>(p);
}

// =====================================================================
// Kernel 0: bake W1 -> g_W1b[g][co][k] as tf32 (cvt.rn).  g = tap*8+cib.
// =====================================================================
__global__ void __launch_bounds__(256) prep_w1(const float* __restrict__ W1)
{
    int idx = blockIdx.x * 256 + threadIdx.x;     // 392*4096
    int g = idx >> 12, e = idx & 4095;
    int co = e >> 5, k = e & 31;
    int tap = g >> 3, cib = g & 7;
    float wv = W1[((size_t)co * CC + cib * 32 + k) * NT + tap];
    g_W1b[idx] = __uint_as_float(cvt_tf32(wv));
}

// =====================================================================
// Kernel A: conv1 tf32 mma.sync GEMM. Grid (98, 3), 256 threads (8 warps).
// CTA tile 128px x 128co; warp tile 64x32 (acc=64 regs, no reg cap).
// Each warp does the full k=32 of each group. K-split 3 via grid.y.
// =====================================================================
#define ASTRIDE 36
#define ABYTES  (128 * ASTRIDE * 4)     // 18432
#define CONV1_SMEM (4 * ABYTES)         // 73728

__global__ void __launch_bounds__(256, 1) conv1_mma(const float* __restrict__ x)
{
    extern __shared__ __align__(16) char smem[];
    float* const As0 = (float*)smem;
    float* const Bs0 = (float*)(smem + 2 * ABYTES);

    const int tid = threadIdx.x;
    const int wid = tid >> 5, lane = tid & 31;
    const int g8 = lane >> 2, t4 = lane & 3;
    const int m0 = (wid >> 2) * 64;       // M half
    const int n0 = (wid & 3) * 32;        // N quarter

    const int q = blockIdx.y;
    const int gstart = q * 131;
    const int gend = (q == KSPL - 1) ? GTOT : (gstart + 131);

    // A loading role: 2 threads per pixel row (16 k each)
    const int r = tid >> 1;
    const int kh16 = (tid & 1) * 16;
    const int px = blockIdx.x * 128 + r;
    const int b = px / HW, rem = px % HW;
    const int h = rem / WW, w0 = rem % WW;

    const uint32_t sb = smem_to_u32(smem);
    const uint32_t a_st_base = sb + (uint32_t)(r * ASTRIDE + kh16) * 4;
    const uint32_t b_cp_base = sb + 2 * (uint32_t)ABYTES;

    float acc[4][4][4];
#pragma unroll
    for (int i = 0; i < 4; ++i)
#pragma unroll
        for (int j = 0; j < 4; ++j)
#pragma unroll
            for (int c = 0; c < 4; ++c) acc[i][j][c] = 0.f;

    float v[16];

    auto lda = [&](int g) {
        int tap = g >> 3, cib = g & 7;
        int di = tap / 7, dj = tap - di * 7;
        int ir = h - 6 + 2 * di, ic = w0 - 6 + 2 * dj;
        bool ok = ((unsigned)ir < HH) && ((unsigned)ic < WW);
        const float* xb = x + ((size_t)(b * CC + cib * 32 + kh16)) * HW + ir * WW + ic;
#pragma unroll
        for (int k = 0; k < 16; ++k)
            v[k] = ok ? __ldg(xb + (size_t)k * HW) : 0.f;
    };
    auto ldb = [&](int g, int buf) {
        const char* src = (const char*)(g_W1b + (size_t)g * 4096);
        uint32_t dstb = b_cp_base + (uint32_t)buf * ABYTES;
#pragma unroll
        for (int i = 0; i < 4; ++i) {
            int c = tid + i * 256;            // float4 chunk 0..1023
            int co = c >> 3, kq = c & 7;
            uint32_t d = dstb + (uint32_t)(co * ASTRIDE + kq * 4) * 4;
            CP16(d, src + (size_t)c * 16);
        }
    };
    auto sta = [&](int buf) {
        uint32_t dst = a_st_base + (uint32_t)buf * ABYTES;
#pragma unroll
        for (int k = 0; k < 16; k += 4)
            sts128(dst + k * 4, cvt_tf32(v[k]), cvt_tf32(v[k + 1]),
                   cvt_tf32(v[k + 2]), cvt_tf32(v[k + 3]));
    };

    // prologue
    lda(gstart); ldb(gstart, 0); CP_COMMIT();
    sta(0);
    CP_WAIT0();
    __syncthreads();

    for (int g = gstart; g < gend; ++g) {
        const int cur = (g - gstart) & 1;
        if (g + 1 < gend) { lda(g + 1); ldb(g + 1, cur ^ 1); CP_COMMIT(); }

        const float* ap = As0 + (size_t)cur * (ABYTES / 4) + m0 * ASTRIDE;
        const float* bp = Bs0 + (size_t)cur * (ABYTES / 4) + n0 * ASTRIDE;
#pragma unroll
        for (int kk = 0; kk < 4; ++kk) {
            const int k0 = kk * 8;
            uint32_t af[4][4], bf[4][2];
#pragma unroll
            for (int i = 0; i < 4; ++i) {
                const float* ar = ap + (16 * i + g8) * ASTRIDE + k0 + t4;
                af[i][0] = __float_as_uint(ar[0]);
                af[i][1] = __float_as_uint(ar[8 * ASTRIDE]);
                af[i][2] = __float_as_uint(ar[4]);
                af[i][3] = __float_as_uint(ar[8 * ASTRIDE + 4]);
            }
#pragma unroll
            for (int j = 0; j < 4; ++j) {
                const float* br = bp + (8 * j + g8) * ASTRIDE + k0 + t4;
                bf[j][0] = __float_as_uint(br[0]);
                bf[j][1] = __float_as_uint(br[4]);
            }
#pragma unroll
            for (int i = 0; i < 4; ++i)
#pragma unroll
                for (int j = 0; j < 4; ++j)
                    MMA_TF32(acc[i][j], af[i], bf[j]);
        }

        if (g + 1 < gend) { sta(cur ^ 1); CP_WAIT0(); }
        __syncthreads();
    }

    // ---- epilogue: write acc to smem [co][px] (stride 132), then STG ----
    float* const Cs = (float*)smem;
#pragma unroll
    for (int i = 0; i < 4; ++i)
#pragma unroll
        for (int j = 0; j < 4; ++j) {
            int row0 = m0 + 16 * i + g8;
            int col0 = n0 + 8 * j + 2 * t4;
            Cs[(col0)     * 132 + row0]     = acc[i][j][0];
            Cs[(col0 + 1) * 132 + row0]     = acc[i][j][1];
            Cs[(col0)     * 132 + row0 + 8] = acc[i][j][2];
            Cs[(col0 + 1) * 132 + row0 + 8] = acc[i][j][3];
        }
    __syncthreads();

    {
        const int pxl = tid & 127, ch = tid >> 7;
        const int pxg = blockIdx.x * 128 + pxl;
        const int b2 = pxg / HW, rem2 = pxg % HW;
        float* base = g_part + ((size_t)(q * BB + b2) * CO) * HW + rem2;
#pragma unroll 4
        for (int co = ch * 64; co < ch * 64 + 64; ++co)
            base[(size_t)co * HW] = Cs[co * 132 + pxl];
    }
}

// =====================================================================
// Kernel B: sum 3 K-split slices + b1, conv2 (1x1) + b2, softmax(49)
// =====================================================================
__global__ void __launch_bounds__(256) conv2_softmax_kernel(
    const float* __restrict__ W2, const float* __restrict__ b1,
    const float* __restrict__ b2)
{
    __shared__ float k1s[128][57];
    __shared__ float ls[49][57];
    const int h = blockIdx.x, b = blockIdx.y, tid = threadIdx.x;

    for (int t = tid; t < 128 * 56; t += 256) {
        int c = t / 56, p = t - c * 56;
        size_t base = (size_t)(b * CO + c) * HW + h * WW + p;
        float v = b1[c];
#pragma unroll
        for (int q = 0; q < KSPL; ++q)
            v += g_part[(size_t)q * BB * CO * HW + base];
        k1s[c][p] = v;
    }
    __syncthreads();

    for (int idx = tid; idx < 49 * 56; idx += 256) {
        int kk = idx / 56, p = idx - kk * 56;
        float acc = b2[kk];
        const float* wr = &W2[kk * 128];
#pragma unroll 8
        for (int c = 0; c < 128; ++c) acc += __ldg(&wr[c]) * k1s[c][p];
        ls[kk][p] = acc;
    }
    __syncthreads();

    if (tid < 56) {
        int p = tid;
        float m = -1e30f;
#pragma unroll
        for (int kk = 0; kk < 49; ++kk) m = fmaxf(m, ls[kk][p]);
        float s = 0.f;
#pragma unroll
        for (int kk = 0; kk < 49; ++kk) {
            float e = expf(ls[kk][p] - m);
            ls[kk][p] = e;
            s += e;
        }
        float inv = 1.f / s;
#pragma unroll
        for (int kk = 0; kk < 49; ++kk) ls[kk][p] *= inv;
    }
    __syncthreads();

    for (int t = tid; t < 49 * 56; t += 256) {
        int kk = t / 56, p = t - kk * 56;
        g_attn[((size_t)b * NT + kk) * HW + h * WW + p] = ls[kk][p];
    }
}

// =====================================================================
// Kernel C: weighted local sum over 49 dilated taps -> out
// Grid (56, 4, 2), 224 threads. Thread = 2 channels x 2 px (attn reuse).
// =====================================================================
__global__ void __launch_bounds__(224) gather_kernel(
    const float* __restrict__ x, float* __restrict__ out)
{
    __shared__ __align__(16) float at[49][58];
    __shared__ __align__(16) float xs[16][7][68];
    const int h = blockIdx.x, b = blockIdx.y;
    const int chalf = blockIdx.z * 128;
    const int tid = threadIdx.x;

    for (int t = tid; t < 49 * 56; t += 224) {
        int kk = t / 56, p = t - kk * 56;
        at[kk][p] = g_attn[((size_t)b * NT + kk) * HW + h * WW + p];
    }

    const int pg = tid % 28, cg = tid / 28;   // 28 px-pairs x 8 channel-pairs
    const int p0 = pg * 2;
    const int c0 = cg * 2, c1 = cg * 2 + 1;

    for (int ch = 0; ch < 8; ++ch) {
        __syncthreads();
        for (int t = tid; t < 16 * 476; t += 224) {
            int c = t / 476, rr = t - c * 476;
            int i = rr / 68, col = rr - i * 68;
            int row = h - 6 + 2 * i, gcol = col - 6;
            float v = 0.f;
            if ((unsigned)row < HH && (unsigned)gcol < WW)
                v = x[((size_t)(b * CC + chalf + ch * 16 + c)) * HW + row * WW + gcol];
            xs[c][i][col] = v;
        }
        __syncthreads();

        u64 a0 = 0ull, a1 = 0ull;
#pragma unroll
        for (int i = 0; i < 7; ++i) {
            const float* xr0 = &xs[c0][i][p0];
            const float* xr1 = &xs[c1][i][p0];
#pragma unroll
            for (int j = 0; j < 7; ++j) {
                u64 av = lds64(&at[i * 7 + j][p0]);
                fma2(a0, av, lds64(xr0 + 2 * j));
                fma2(a1, av, lds64(xr1 + 2 * j));
            }
        }
        size_t o0 = (size_t)(b * CC + chalf + ch * 16 + c0) * HW + h * WW + p0;
        size_t o1 = (size_t)(b * CC + chalf + ch * 16 + c1) * HW + h * WW + p0;
        *reinterpret_cast<float2*>(&out[o0]) = unpack2(a0);
        *reinterpret_cast<float2*>(&out[o1]) = unpack2(a1);
    }
}

// =====================================================================
extern "C" void kernel_launch(void* const* d_in, const int* in_sizes, int n_in,
                              void* d_out, int out_size)
{
    const float* x  = (const float*)d_in[0];
    const float* W1 = (const float*)d_in[1];
    const float* b1 = (const float*)d_in[2];
    const float* W2 = (const float*)d_in[3];
    const float* b2 = (const float*)d_in[4];
    for (int i = 0; i < n_in; ++i) {
        switch (in_sizes[i]) {
            case BB * CC * HW: x  = (const float*)d_in[i]; break;
            case CO * CC * NT: W1 = (const float*)d_in[i]; break;
            case CO:           b1 = (const float*)d_in[i]; break;
            case NT * CO:      W2 = (const float*)d_in[i]; break;
            case NT:           b2 = (const float*)d_in[i]; break;
            default: break;
        }
    }
    float* out = (float*)d_out;

    cudaFuncSetAttribute(conv1_mma, cudaFuncAttributeMaxDynamicSharedMemorySize,
                         CONV1_SMEM);
    prep_w1<<<6272, 256>>>(W1);
    conv1_mma<<<dim3(98, KSPL), 256, CONV1_SMEM>>>(x);
    conv2_softmax_kernel<<<dim3(56, 4), 256>>>(W2, b1, b2);
    gather_kernel<<<dim3(56, 4, 2), 224>>>(x, out);
}

// round 8
// speedup vs baseline: 2.1118x; 1.0289x over previous
#include <cuda_runtime.h>
#include <cstdint>

#define BB 4
#define CC 256
#define HH 56
#define WW 56
#define CO 128
#define NT 49
#define HW 3136
#define GTOT 392          // 49 taps x 8 ci-blocks of 32
#define KSPL 3

typedef unsigned long long u64;

// ---- device-global scratch ----
__device__ __align__(16) float g_W1b[GTOT * 4096];          // tf32 weights [g][co][k]
__device__ __align__(16) float g_part[KSPL * BB * CO * HW]; // conv1 K-split partials
__device__ __align__(16) float g_attn[BB * NT * HW];        // softmax attention

// ---------- helpers ----------
__device__ __forceinline__ uint32_t smem_to_u32(const void* p) {
    uint32_t a;
    asm("{ .reg .u64 t; cvta.to.shared.u64 t, %1; cvt.u32.u64 %0, t; }" : "=r"(a) : "l"(p));
    return a;
}
__device__ __forceinline__ uint32_t cvt_tf32(float f) {
    uint32_t u;
    asm("cvt.rn.tf32.f32 %0, %1;" : "=r"(u) : "f"(f));
    return u;
}
#define CP16(dst, src) \
    asm volatile("cp.async.cg.shared.global [%0], [%1], 16;" :: "r"(dst), "l"(src) : "memory")
#define CP_COMMIT() asm volatile("cp.async.commit_group;" ::: "memory")
#define CP_WAIT0()  asm volatile("cp.async.wait_group 0;" ::: "memory")

#define MMA_TF32(d, a, bfr) \
    asm volatile("mma.sync.aligned.m16n8k8.row.col.f32.tf32.tf32.f32 " \
        "{%0,%1,%2,%3}, {%4,%5,%6,%7}, {%8,%9}, {%0,%1,%2,%3};" \
        : "+f"((d)[0]), "+f"((d)[1]), "+f"((d)[2]), "+f"((d)[3]) \
        : "r"((a)[0]), "r"((a)[1]), "r"((a)[2]), "r"((a)[3]), \
          "r"((bfr)[0]), "r"((bfr)[1]))

__device__ __forceinline__ void sts128(uint32_t a, uint32_t r0, uint32_t r1,
                                       uint32_t r2, uint32_t r3) {
    asm volatile("st.shared.v4.b32 [%0], {%1,%2,%3,%4};"
                 :: "r"(a), "r"(r0), "r"(r1), "r"(r2), "r"(r3) : "memory");
}
// ---------- f32x2 helpers for scalar kernels ----------
__device__ __forceinline__ void fma2(u64& d, u64 a, u64 b) {
    asm("fma.rn.f32x2 %0, %1, %2, %0;" : "+l"(d) : "l"(a), "l"(b));
}
__device__ __forceinline__ float2 unpack2(u64 v) {
    float2 f;
    asm("mov.b64 {%0, %1}, %2;" : "=f"(f.x), "=f"(f.y) : "l"(v));
    return f;
}
__device__ __forceinline__ u64 lds64(const float* p) {
    return *reinterpret_cast<const u64*>(p);
}

// =====================================================================
// Kernel 0: bake W1 -> g_W1b[g][co][k] as tf32 (cvt.rn).  g = tap*8+cib.
// =====================================================================
__global__ void __launch_bounds__(256) prep_w1(const float* __restrict__ W1)
{
    int idx = blockIdx.x * 256 + threadIdx.x;     // 392*4096
    int g = idx >> 12, e = idx & 4095;
    int co = e >> 5, k = e & 31;
    int tap = g >> 3, cib = g & 7;
    float wv = W1[((size_t)co * CC + cib * 32 + k) * NT + tap];
    g_W1b[idx] = __uint_as_float(cvt_tf32(wv));
}

// =====================================================================
// Kernel A: conv1 tf32 mma.sync GEMM. Grid (98, 3), 256 threads (8 warps).
// CTA tile 128px x 128co; warp tile 64x32. A smem transposed: As[k][px]
// (stride 136 -> conflict-free frags + vectorized pixel loads).
// =====================================================================
#define AST 136
#define A_BYTES (32 * AST * 4)          // 17408
#define BST 36
#define B_BYTES (128 * BST * 4)         // 18432
#define CONV1_SMEM (2 * A_BYTES + 2 * B_BYTES)   // 71680

__global__ void __launch_bounds__(256, 2) conv1_mma(const float* __restrict__ x)
{
    extern __shared__ __align__(16) char smem[];
    float* const As0 = (float*)smem;
    float* const Bs0 = (float*)(smem + 2 * A_BYTES);

    const int tid = threadIdx.x;
    const int wid = tid >> 5, lane = tid & 31;
    const int g8 = lane >> 2, t4 = lane & 3;
    const int m0 = (wid >> 2) * 64;       // M half
    const int n0 = (wid & 3) * 32;        // N quarter

    const int q = blockIdx.y;
    const int gstart = q * 131;
    const int gend = (q == KSPL - 1) ? GTOT : (gstart + 131);

    // A loading role: one 4-pixel quad (ql) x 4 k values (kb + 8*it)
    const int ql = tid & 31, kb = tid >> 5;       // kb uniform per warp
    const int px4 = ql * 4;
    const int gp = blockIdx.x * 128 + px4;
    const int b4 = gp / HW, rem4 = gp % HW;
    const int h4 = rem4 / WW, w4 = rem4 % WW;     // w4 multiple of 4

    const uint32_t sb = smem_to_u32(smem);
    const uint32_t a_st_base = sb + (uint32_t)px4 * 4;
    const uint32_t b_cp_base = sb + 2 * (uint32_t)A_BYTES;

    float acc[4][4][4];
#pragma unroll
    for (int i = 0; i < 4; ++i)
#pragma unroll
        for (int j = 0; j < 4; ++j)
#pragma unroll
            for (int c = 0; c < 4; ++c) acc[i][j][c] = 0.f;

    float2 v2[4][2];

    auto lda = [&](int g) {
        int tap = g >> 3, cib = g & 7;
        int di = tap / 7, dj = tap - di * 7;
        int ir = h4 - 6 + 2 * di;
        int ic0 = w4 - 6 + 2 * dj;                 // always even -> 8B aligned
        bool rowok = ((unsigned)ir < HH);
        const float* src = x + ((size_t)(b4 * CC + cib * 32 + kb)) * HW
                             + ir * WW + ic0;
        if (rowok && ic0 >= 0 && ic0 <= WW - 4) {
#pragma unroll
            for (int it = 0; it < 4; ++it) {
                const float* s = src + (size_t)(8 * it) * HW;
                v2[it][0] = *reinterpret_cast<const float2*>(s);
                v2[it][1] = *reinterpret_cast<const float2*>(s + 2);
            }
        } else {
#pragma unroll
            for (int it = 0; it < 4; ++it) {
                const float* s = src + (size_t)(8 * it) * HW;
                v2[it][0].x = (rowok && ic0 >= 0 && ic0 < WW)         ? __ldg(s)     : 0.f;
                v2[it][0].y = (rowok && ic0 + 1 >= 0 && ic0 + 1 < WW) ? __ldg(s + 1) : 0.f;
                v2[it][1].x = (rowok && ic0 + 2 >= 0 && ic0 + 2 < WW) ? __ldg(s + 2) : 0.f;
                v2[it][1].y = (rowok && ic0 + 3 >= 0 && ic0 + 3 < WW) ? __ldg(s + 3) : 0.f;
            }
        }
    };
    auto ldb = [&](int g, int buf) {
        const char* src = (const char*)(g_W1b + (size_t)g * 4096);
        uint32_t dstb = b_cp_base + (uint32_t)buf * B_BYTES;
#pragma unroll
        for (int i = 0; i < 4; ++i) {
            int c = tid + i * 256;            // float4 chunk 0..1023
            int co = c >> 3, kq = c & 7;
            uint32_t d = dstb + (uint32_t)(co * BST + kq * 4) * 4;
            CP16(d, src + (size_t)c * 16);
        }
    };
    auto sta = [&](int buf) {
        uint32_t dst = a_st_base + (uint32_t)buf * A_BYTES;
#pragma unroll
        for (int it = 0; it < 4; ++it) {
            int k = kb + 8 * it;
            sts128(dst + (uint32_t)k * (AST * 4),
                   cvt_tf32(v2[it][0].x), cvt_tf32(v2[it][0].y),
                   cvt_tf32(v2[it][1].x), cvt_tf32(v2[it][1].y));
        }
    };

    // prologue
    lda(gstart); ldb(gstart, 0); CP_COMMIT();
    sta(0);
    CP_WAIT0();
    __syncthreads();

    for (int g = gstart; g < gend; ++g) {
        const int cur = (g - gstart) & 1;
        if (g + 1 < gend) { lda(g + 1); ldb(g + 1, cur ^ 1); CP_COMMIT(); }

        const float* ap = As0 + (size_t)cur * (A_BYTES / 4) + m0;
        const float* bp = Bs0 + (size_t)cur * (B_BYTES / 4) + n0 * BST;
#pragma unroll
        for (int kk = 0; kk < 4; ++kk) {
            const int k0 = kk * 8;
            uint32_t af[4][4], bf[4][2];
#pragma unroll
            for (int i = 0; i < 4; ++i) {
                const float* ar = ap + (k0 + t4) * AST + 16 * i + g8;
                af[i][0] = __float_as_uint(ar[0]);
                af[i][1] = __float_as_uint(ar[8]);
                af[i][2] = __float_as_uint(ar[4 * AST]);
                af[i][3] = __float_as_uint(ar[4 * AST + 8]);
            }
#pragma unroll
            for (int j = 0; j < 4; ++j) {
                const float* br = bp + (8 * j + g8) * BST + k0 + t4;
                bf[j][0] = __float_as_uint(br[0]);
                bf[j][1] = __float_as_uint(br[4]);
            }
#pragma unroll
            for (int i = 0; i < 4; ++i)
#pragma unroll
                for (int j = 0; j < 4; ++j)
                    MMA_TF32(acc[i][j], af[i], bf[j]);
        }

        if (g + 1 < gend) { sta(cur ^ 1); CP_WAIT0(); }
        __syncthreads();
    }

    // ---- epilogue: write acc to smem [co][px] (stride 132), then STG ----
    float* const Cs = (float*)smem;
#pragma unroll
    for (int i = 0; i < 4; ++i)
#pragma unroll
        for (int j = 0; j < 4; ++j) {
            int row0 = m0 + 16 * i + g8;
            int col0 = n0 + 8 * j + 2 * t4;
            Cs[(col0)     * 132 + row0]     = acc[i][j][0];
            Cs[(col0 + 1) * 132 + row0]     = acc[i][j][1];
            Cs[(col0)     * 132 + row0 + 8] = acc[i][j][2];
            Cs[(col0 + 1) * 132 + row0 + 8] = acc[i][j][3];
        }
    __syncthreads();

    {
        const int pxl = tid & 127, ch = tid >> 7;
        const int pxg = blockIdx.x * 128 + pxl;
        const int b2 = pxg / HW, rem2 = pxg % HW;
        float* base = g_part + ((size_t)(q * BB + b2) * CO) * HW + rem2;
#pragma unroll 4
        for (int co = ch * 64; co < ch * 64 + 64; ++co)
            base[(size_t)co * HW] = Cs[co * 132 + pxl];
    }
}

// =====================================================================
// Kernel B: sum 3 K-split slices + b1, conv2 (1x1) + b2, softmax(49)
// =====================================================================
__global__ void __launch_bounds__(256) conv2_softmax_kernel(
    const float* __restrict__ W2, const float* __restrict__ b1,
    const float* __restrict__ b2)
{
    __shared__ float k1s[128][57];
    __shared__ float ls[49][57];
    const int h = blockIdx.x, b = blockIdx.y, tid = threadIdx.x;

    for (int t = tid; t < 128 * 56; t += 256) {
        int c = t / 56, p = t - c * 56;
        size_t base = (size_t)(b * CO + c) * HW + h * WW + p;
        float v = b1[c];
#pragma unroll
        for (int q = 0; q < KSPL; ++q)
            v += g_part[(size_t)q * BB * CO * HW + base];
        k1s[c][p] = v;
    }
    __syncthreads();

    for (int idx = tid; idx < 49 * 56; idx += 256) {
        int kk = idx / 56, p = idx - kk * 56;
        float acc = b2[kk];
        const float* wr = &W2[kk * 128];
#pragma unroll 8
        for (int c = 0; c < 128; ++c) acc += __ldg(&wr[c]) * k1s[c][p];
        ls[kk][p] = acc;
    }
    __syncthreads();

    if (tid < 56) {
        int p = tid;
        float m = -1e30f;
#pragma unroll
        for (int kk = 0; kk < 49; ++kk) m = fmaxf(m, ls[kk][p]);
        float s = 0.f;
#pragma unroll
        for (int kk = 0; kk < 49; ++kk) {
            float e = expf(ls[kk][p] - m);
            ls[kk][p] = e;
            s += e;
        }
        float inv = 1.f / s;
#pragma unroll
        for (int kk = 0; kk < 49; ++kk) ls[kk][p] *= inv;
    }
    __syncthreads();

    for (int t = tid; t < 49 * 56; t += 256) {
        int kk = t / 56, p = t - kk * 56;
        g_attn[((size_t)b * NT + kk) * HW + h * WW + p] = ls[kk][p];
    }
}

// =====================================================================
// Kernel C: weighted local sum over 49 dilated taps -> out
// Grid (56, 4, 2), 224 threads. Thread = 2 channels x 2 px.
// Incremental x-tile loader (no per-element div/mod).
// =====================================================================
__global__ void __launch_bounds__(224) gather_kernel(
    const float* __restrict__ x, float* __restrict__ out)
{
    __shared__ __align__(16) float at[49][58];
    __shared__ __align__(16) float xs[112][68];   // [c*7+i][col]
    const int h = blockIdx.x, b = blockIdx.y;
    const int chalf = blockIdx.z * 128;
    const int tid = threadIdx.x;

    for (int t = tid; t < 49 * 56; t += 224) {
        int kk = t / 56, p = t - kk * 56;
        at[kk][p] = g_attn[((size_t)b * NT + kk) * HW + h * WW + p];
    }

    // loader role (fixed): row-stride-3 walker, coalesced over col
    const int r_off = tid / 68;               // 0..3 (>=3 -> inactive)
    const int lcol = tid - r_off * 68;
    const bool lactive = (r_off < 3);
    const bool colv = (lcol >= 6 && lcol < 62);
    const int gcol = lcol - 6;

    // compute role
    const int pg = tid % 28, cg = tid / 28;   // 28 px-pairs x 8 channel-pairs
    const int p0 = pg * 2;
    const int c0 = cg * 2, c1 = c0 + 1;

    for (int ch = 0; ch < 8; ++ch) {
        __syncthreads();
        if (lactive) {
            const float* xc = x + ((size_t)(b * CC + chalf + ch * 16)) * HW + gcol;
            int r = r_off, i = r_off;
            int off = (h - 6 + 2 * i) * WW;   // row offset, c=0
            int cHW = 0;
            uint32_t dst = smem_to_u32(xs) + (uint32_t)(r * 68 + lcol) * 4;
#pragma unroll 2
            for (int itr = 0; itr < 38; ++itr) {
                if (r < 112) {
                    int row = h - 6 + 2 * i;
                    float v = ((unsigned)row < HH && colv) ? __ldg(xc + cHW + off) : 0.f;
                    asm volatile("st.shared.f32 [%0], %1;" :: "r"(dst), "f"(v) : "memory");
                }
                r += 3; i += 3; off += 6 * WW;
                if (i >= 7) { i -= 7; cHW += HW; off -= 14 * WW; }
                dst += 3 * 68 * 4;
            }
        }
        __syncthreads();

        u64 a0 = 0ull, a1 = 0ull;
#pragma unroll
        for (int i = 0; i < 7; ++i) {
            const float* xr0 = &xs[c0 * 7 + i][p0];
            const float* xr1 = &xs[c1 * 7 + i][p0];
#pragma unroll
            for (int j = 0; j < 7; ++j) {
                u64 av = lds64(&at[i * 7 + j][p0]);
                fma2(a0, av, lds64(xr0 + 2 * j));
                fma2(a1, av, lds64(xr1 + 2 * j));
            }
        }
        size_t o0 = (size_t)(b * CC + chalf + ch * 16 + c0) * HW + h * WW + p0;
        size_t o1 = (size_t)(b * CC + chalf + ch * 16 + c1) * HW + h * WW + p0;
        *reinterpret_cast<float2*>(&out[o0]) = unpack2(a0);
        *reinterpret_cast<float2*>(&out[o1]) = unpack2(a1);
    }
}

// =====================================================================
extern "C" void kernel_launch(void* const* d_in, const int* in_sizes, int n_in,
                              void* d_out, int out_size)
{
    const float* x  = (const float*)d_in[0];
    const float* W1 = (const float*)d_in[1];
    const float* b1 = (const float*)d_in[2];
    const float* W2 = (const float*)d_in[3];
    const float* b2 = (const float*)d_in[4];
    for (int i = 0; i < n_in; ++i) {
        switch (in_sizes[i]) {
            case BB * CC * HW: x  = (const float*)d_in[i]; break;
            case CO * CC * NT: W1 = (const float*)d_in[i]; break;
            case CO:           b1 = (const float*)d_in[i]; break;
            case NT * CO:      W2 = (const float*)d_in[i]; break;
            case NT:           b2 = (const float*)d_in[i]; break;
            default: break;
        }
    }
    float* out = (float*)d_out;

    cudaFuncSetAttribute(conv1_mma, cudaFuncAttributeMaxDynamicSharedMemorySize,
                         CONV1_SMEM);
    prep_w1<<<6272, 256>>>(W1);
    conv1_mma<<<dim3(98, KSPL), 256, CONV1_SMEM>>>(x);
    conv2_softmax_kernel<<<dim3(56, 4), 256>>>(W2, b1, b2);
    gather_kernel<<<dim3(56, 4, 2), 224>>>(x, out);
}

// round 9
// speedup vs baseline: 2.4579x; 1.1639x over previous
#include <cuda_runtime.h>
#include <cstdint>

#define BB 4
#define CC 256
#define HH 56
#define WW 56
#define CO 128
#define NT 49
#define HW 3136
#define GTOT 392          // 49 taps x 8 ci-blocks of 32
#define KSPL 3
#define XPR 68            // padded image 68x68
#define XPCH (XPR * XPR)  // 4624
#define NPC (BB * CC * XPCH)

typedef unsigned long long u64;

// ---- device-global scratch ----
__device__ __align__(16) float g_W1b[GTOT * 4096];          // tf32 weights [g][co][k]
__device__ __align__(16) float g_xpad[2 * NPC];             // padded x, 2 parities
__device__ __align__(16) float g_part[KSPL * BB * CO * HW]; // conv1 K-split partials
__device__ __align__(16) float g_attn[BB * NT * HW];        // softmax attention

// ---------- helpers ----------
__device__ __forceinline__ uint32_t smem_to_u32(const void* p) {
    uint32_t a;
    asm("{ .reg .u64 t; cvta.to.shared.u64 t, %1; cvt.u32.u64 %0, t; }" : "=r"(a) : "l"(p));
    return a;
}
__device__ __forceinline__ uint32_t cvt_tf32(float f) {
    uint32_t u;
    asm("cvt.rn.tf32.f32 %0, %1;" : "=r"(u) : "f"(f));
    return u;
}
#define CP16(dst, src) \
    asm volatile("cp.async.cg.shared.global [%0], [%1], 16;" :: "r"(dst), "l"(src) : "memory")
#define CP_COMMIT() asm volatile("cp.async.commit_group;" ::: "memory")
#define CP_WAIT0()  asm volatile("cp.async.wait_group 0;" ::: "memory")
#define CP_WAIT1()  asm volatile("cp.async.wait_group 1;" ::: "memory")

#define MMA_TF32(d, a, bfr) \
    asm volatile("mma.sync.aligned.m16n8k8.row.col.f32.tf32.tf32.f32 " \
        "{%0,%1,%2,%3}, {%4,%5,%6,%7}, {%8,%9}, {%0,%1,%2,%3};" \
        : "+f"((d)[0]), "+f"((d)[1]), "+f"((d)[2]), "+f"((d)[3]) \
        : "r"((a)[0]), "r"((a)[1]), "r"((a)[2]), "r"((a)[3]), \
          "r"((bfr)[0]), "r"((bfr)[1]))

// ---------- f32x2 helpers for scalar kernels ----------
__device__ __forceinline__ void fma2(u64& d, u64 a, u64 b) {
    asm("fma.rn.f32x2 %0, %1, %2, %0;" : "+l"(d) : "l"(a), "l"(b));
}
__device__ __forceinline__ float2 unpack2(u64 v) {
    float2 f;
    asm("mov.b64 {%0, %1}, %2;" : "=f"(f.x), "=f"(f.y) : "l"(v));
    return f;
}
__device__ __forceinline__ u64 lds64(const float* p) {
    return *reinterpret_cast<const u64*>(p);
}

// =====================================================================
// Kernel 0a: bake W1 -> g_W1b[g][co][k] as tf32 (cvt.rn).  g = tap*8+cib.
// =====================================================================
__global__ void __launch_bounds__(256) prep_w1(const float* __restrict__ W1)
{
    int idx = blockIdx.x * 256 + threadIdx.x;     // 392*4096
    int g = idx >> 12, e = idx & 4095;
    int co = e >> 5, k = e & 31;
    int tap = g >> 3, cib = g & 7;
    float wv = W1[((size_t)co * CC + cib * 32 + k) * NT + tap];
    g_W1b[idx] = __uint_as_float(cvt_tf32(wv));
}

// =====================================================================
// Kernel 0b: zero-padded x images. xp0[r][c'] = x[r-6][c'-6];
// xp1[r][c'] = x[r-6][c'-4] (2-col shift for odd-tap 16B alignment).
// =====================================================================
__global__ void __launch_bounds__(256) prep_xpad(const float* __restrict__ x)
{
    int idx = blockIdx.x * 256 + threadIdx.x;
    if (idx >= NPC) return;
    int col = idx % XPR;
    int t = idx / XPR;
    int r = t % XPR;
    int bc = t / XPR;
    int rr = r - 6;
    float v0 = 0.f, v1 = 0.f;
    if ((unsigned)rr < HH) {
        const float* xr = x + (size_t)bc * HW + rr * WW;
        int c0 = col - 6;
        if ((unsigned)c0 < WW) v0 = __ldg(xr + c0);
        int c1 = col - 4;
        if ((unsigned)c1 < WW) v1 = __ldg(xr + c1);
    }
    g_xpad[idx] = v0;
    g_xpad[NPC + idx] = v1;
}

// =====================================================================
// Kernel A: conv1 tf32 mma.sync GEMM, all-cp.async, 3-stage pipeline.
// Grid (98, 3), 256 threads (8 warps). CTA tile 128px x 128co; warp 64x32.
// A: As[k][px] stride 136, filled by guard-free cp.async from g_xpad.
// =====================================================================
#define AST 136
#define A_BYTES (32 * AST * 4)          // 17408
#define BST 36
#define B_BYTES (128 * BST * 4)         // 18432
#define NST 3
#define CONV1_SMEM (NST * (A_BYTES + B_BYTES))   // 107520

__global__ void __launch_bounds__(256, 2) conv1_mma()
{
    extern __shared__ __align__(16) char smem[];
    const uint32_t sb = smem_to_u32(smem);
    const uint32_t sbB = sb + NST * A_BYTES;

    const int tid = threadIdx.x;
    const int wid = tid >> 5, lane = tid & 31;
    const int g8 = lane >> 2, t4 = lane & 3;
    const int m0 = (wid >> 2) * 64;       // M half
    const int n0 = (wid & 3) * 32;        // N quarter

    const int q = blockIdx.y;
    const int gstart = q * 131;
    const int gend = (gstart + 131 > GTOT) ? GTOT : (gstart + 131);
    const int n = gend - gstart;

    // A-copy role: pixel quad (qd) x k-slot (kl, +8 per it)
    const int kl = tid >> 5;
    const int qd = tid & 31;
    const int gp = blockIdx.x * 128 + qd * 4;
    const int b4 = gp / HW, rem4 = gp % HW;
    const int h4 = rem4 / WW, w4 = rem4 % WW;       // w4 multiple of 4
    const float* const aBase = g_xpad + (size_t)(b4 * CC + kl) * XPCH + h4 * XPR + w4;
    const uint32_t a_dst0 = sb + (uint32_t)(kl * AST + qd * 4) * 4;

    auto issue = [&](int g, int s) {
        // ---- B: 16KB tile ----
        const char* srcB = (const char*)(g_W1b + (size_t)g * 4096);
        uint32_t dstb = sbB + (uint32_t)s * B_BYTES;
#pragma unroll
        for (int i2 = 0; i2 < 4; ++i2) {
            int c = tid + i2 * 256;
            int co = c >> 3, kk2 = c & 7;
            CP16(dstb + (uint32_t)(co * BST + kk2 * 4) * 4, srcB + (size_t)c * 16);
        }
        // ---- A: 16KB patch tile, guard-free from padded image ----
        int tap = g >> 3, cib = g & 7;
        int di = tap / 7, dj = tap - di * 7;
        int par = dj & 1;
        const float* sA = aBase + (par ? NPC : 0) + (size_t)(cib * 32) * XPCH
                        + di * (2 * XPR) + (2 * dj - 2 * par);
        uint32_t dA = a_dst0 + (uint32_t)s * A_BYTES;
#pragma unroll
        for (int it = 0; it < 4; ++it) {
            CP16(dA, (const char*)sA);
            dA += 8 * AST * 4;
            sA += (size_t)8 * XPCH;
        }
        CP_COMMIT();
    };

    float acc[4][4][4];
#pragma unroll
    for (int i = 0; i < 4; ++i)
#pragma unroll
        for (int j = 0; j < 4; ++j)
#pragma unroll
            for (int c = 0; c < 4; ++c) acc[i][j][c] = 0.f;

    issue(gstart, 0);
    issue(gstart + 1, 1);

    for (int gi = 0; gi < n; ++gi) {
        const int s = gi % NST;
        if (gi + 1 < n) { CP_WAIT1(); } else { CP_WAIT0(); }
        __syncthreads();

        const float* ap = (const float*)(smem + s * A_BYTES) + m0;
        const float* bp = (const float*)(smem + NST * A_BYTES + s * B_BYTES) + n0 * BST;
#pragma unroll
        for (int kk = 0; kk < 4; ++kk) {
            const int k0 = kk * 8;
            uint32_t af[4][4], bf[4][2];
#pragma unroll
            for (int i = 0; i < 4; ++i) {
                const float* ar = ap + (k0 + t4) * AST + 16 * i + g8;
                af[i][0] = __float_as_uint(ar[0]);
                af[i][1] = __float_as_uint(ar[8]);
                af[i][2] = __float_as_uint(ar[4 * AST]);
                af[i][3] = __float_as_uint(ar[4 * AST + 8]);
            }
#pragma unroll
            for (int j = 0; j < 4; ++j) {
                const float* br = bp + (8 * j + g8) * BST + k0 + t4;
                bf[j][0] = __float_as_uint(br[0]);
                bf[j][1] = __float_as_uint(br[4]);
            }
#pragma unroll
            for (int i = 0; i < 4; ++i)
#pragma unroll
                for (int j = 0; j < 4; ++j)
                    MMA_TF32(acc[i][j], af[i], bf[j]);
        }

        if (gi + 2 < n) issue(gstart + gi + 2, (gi + 2) % NST);
    }
    __syncthreads();

    // ---- epilogue: acc -> smem [co][px] (stride 132) -> coalesced STG ----
    float* const Cs = (float*)smem;
#pragma unroll
    for (int i = 0; i < 4; ++i)
#pragma unroll
        for (int j = 0; j < 4; ++j) {
            int row0 = m0 + 16 * i + g8;
            int col0 = n0 + 8 * j + 2 * t4;
            Cs[(col0)     * 132 + row0]     = acc[i][j][0];
            Cs[(col0 + 1) * 132 + row0]     = acc[i][j][1];
            Cs[(col0)     * 132 + row0 + 8] = acc[i][j][2];
            Cs[(col0 + 1) * 132 + row0 + 8] = acc[i][j][3];
        }
    __syncthreads();

    {
        const int pxl = tid & 127, ch = tid >> 7;
        const int pxg = blockIdx.x * 128 + pxl;
        const int b2 = pxg / HW, rem2 = pxg % HW;
        float* base = g_part + ((size_t)(q * BB + b2) * CO) * HW + rem2;
#pragma unroll 4
        for (int co = ch * 64; co < ch * 64 + 64; ++co)
            base[(size_t)co * HW] = Cs[co * 132 + pxl];
    }
}

// =====================================================================
// Kernel B: sum 3 K-split slices + b1, conv2 (1x1) + b2, softmax(49)
// =====================================================================
__global__ void __launch_bounds__(256) conv2_softmax_kernel(
    const float* __restrict__ W2, const float* __restrict__ b1,
    const float* __restrict__ b2)
{
    __shared__ float k1s[128][57];
    __shared__ float ls[49][57];
    const int h = blockIdx.x, b = blockIdx.y, tid = threadIdx.x;

    for (int t = tid; t < 128 * 56; t += 256) {
        int c = t / 56, p = t - c * 56;
        size_t base = (size_t)(b * CO + c) * HW + h * WW + p;
        float v = b1[c];
#pragma unroll
        for (int q = 0; q < KSPL; ++q)
            v += g_part[(size_t)q * BB * CO * HW + base];
        k1s[c][p] = v;
    }
    __syncthreads();

    for (int idx = tid; idx < 49 * 56; idx += 256) {
        int kk = idx / 56, p = idx - kk * 56;
        float acc = b2[kk];
        const float* wr = &W2[kk * 128];
#pragma unroll 8
        for (int c = 0; c < 128; ++c) acc += __ldg(&wr[c]) * k1s[c][p];
        ls[kk][p] = acc;
    }
    __syncthreads();

    if (tid < 56) {
        int p = tid;
        float m = -1e30f;
#pragma unroll
        for (int kk = 0; kk < 49; ++kk) m = fmaxf(m, ls[kk][p]);
        float s = 0.f;
#pragma unroll
        for (int kk = 0; kk < 49; ++kk) {
            float e = expf(ls[kk][p] - m);
            ls[kk][p] = e;
            s += e;
        }
        float inv = 1.f / s;
#pragma unroll
        for (int kk = 0; kk < 49; ++kk) ls[kk][p] *= inv;
    }
    __syncthreads();

    for (int t = tid; t < 49 * 56; t += 256) {
        int kk = t / 56, p = t - kk * 56;
        g_attn[((size_t)b * NT + kk) * HW + h * WW + p] = ls[kk][p];
    }
}

// =====================================================================
// Kernel C: weighted local sum over 49 dilated taps -> out
// Grid (56, 4, 2), 224 threads. Thread = 2 channels x 2 px.
// Guard-free float4 tile loads from padded x.
// =====================================================================
__global__ void __launch_bounds__(224) gather_kernel(float* __restrict__ out)
{
    __shared__ __align__(16) float at[49][60];
    __shared__ __align__(16) float xs[112][68];   // [c*7+i][col], c<16
    const int h = blockIdx.x, b = blockIdx.y;
    const int chalf = blockIdx.z * 128;
    const int tid = threadIdx.x;

    // attn tile: float4 loads (rows 16B-aligned in gmem and smem)
    for (int t = tid; t < 49 * 14; t += 224) {
        int kk = t / 14, p4 = t - kk * 14;
        *reinterpret_cast<float4*>(&at[kk][p4 * 4]) =
            *reinterpret_cast<const float4*>(
                g_attn + ((size_t)b * NT + kk) * HW + h * WW + p4 * 4);
    }

    const int pg = tid % 28, cg = tid / 28;   // 28 px-pairs x 8 channel-pairs
    const int p0 = pg * 2;
    const int c0 = cg * 2, c1 = c0 + 1;

    for (int ch = 0; ch < 8; ++ch) {
        __syncthreads();
        // x tile: 16 ch x 7 rows x 68 cols, guard-free from padded image
        const float* xpc = g_xpad + (size_t)(b * CC + chalf + ch * 16) * XPCH
                         + (size_t)h * XPR;
        for (int t = tid; t < 16 * 7 * 17; t += 224) {
            int c = t / 119;
            int r = t - c * 119;
            int i = r / 17;
            int qd = r - i * 17;
            *reinterpret_cast<float4*>(&xs[c * 7 + i][qd * 4]) =
                *reinterpret_cast<const float4*>(xpc + (size_t)c * XPCH
                                                 + i * (2 * XPR) + qd * 4);
        }
        __syncthreads();

        u64 a0 = 0ull, a1 = 0ull;
#pragma unroll
        for (int i = 0; i < 7; ++i) {
            const float* xr0 = &xs[c0 * 7 + i][p0 + 6];
            const float* xr1 = &xs[c1 * 7 + i][p0 + 6];
#pragma unroll
            for (int j = 0; j < 7; ++j) {
                u64 av = lds64(&at[i * 7 + j][p0]);
                fma2(a0, av, lds64(xr0 + 2 * j - 6));
                fma2(a1, av, lds64(xr1 + 2 * j - 6));
            }
        }
        size_t o0 = (size_t)(b * CC + chalf + ch * 16 + c0) * HW + h * WW + p0;
        size_t o1 = (size_t)(b * CC + chalf + ch * 16 + c1) * HW + h * WW + p0;
        *reinterpret_cast<float2*>(&out[o0]) = unpack2(a0);
        *reinterpret_cast<float2*>(&out[o1]) = unpack2(a1);
    }
}

// =====================================================================
extern "C" void kernel_launch(void* const* d_in, const int* in_sizes, int n_in,
                              void* d_out, int out_size)
{
    const float* x  = (const float*)d_in[0];
    const float* W1 = (const float*)d_in[1];
    const float* b1 = (const float*)d_in[2];
    const float* W2 = (const float*)d_in[3];
    const float* b2 = (const float*)d_in[4];
    for (int i = 0; i < n_in; ++i) {
        switch (in_sizes[i]) {
            case BB * CC * HW: x  = (const float*)d_in[i]; break;
            case CO * CC * NT: W1 = (const float*)d_in[i]; break;
            case CO:           b1 = (const float*)d_in[i]; break;
            case NT * CO:      W2 = (const float*)d_in[i]; break;
            case NT:           b2 = (const float*)d_in[i]; break;
            default: break;
        }
    }
    float* out = (float*)d_out;

    cudaFuncSetAttribute(conv1_mma, cudaFuncAttributeMaxDynamicSharedMemorySize,
                         CONV1_SMEM);
    prep_w1<<<6272, 256>>>(W1);
    prep_xpad<<<(NPC + 255) / 256, 256>>>(x);
    conv1_mma<<<dim3(98, KSPL), 256, CONV1_SMEM>>>();
    conv2_softmax_kernel<<<dim3(56, 4), 256>>>(W2, b1, b2);
    gather_kernel<<<dim3(56, 4, 2), 224>>>(out);
}

// round 10
// speedup vs baseline: 2.5617x; 1.0422x over previous
#include <cuda_runtime.h>
#include <cstdint>

#define BB 4
#define CC 256
#define HH 56
#define WW 56
#define CO 128
#define NT 49
#define HW 3136
#define GTOT 392          // 49 taps x 8 ci-blocks of 32
#define KSPL 3
#define XPR 68            // padded image 68x68
#define XPCH (XPR * XPR)  // 4624
#define NPC (BB * CC * XPCH)

typedef unsigned long long u64;

// ---- device-global scratch ----
__device__ __align__(16) float g_W1b[GTOT * 4096];          // tf32 weights [g][co][k]
__device__ __align__(16) float g_xpad[2 * NPC];             // padded x, 2 parities
__device__ __align__(16) float g_part[KSPL * BB * CO * HW]; // conv1 K-split partials
__device__ __align__(16) float g_attn[BB * NT * HW];        // softmax attention

// ---------- helpers ----------
__device__ __forceinline__ uint32_t smem_to_u32(const void* p) {
    uint32_t a;
    asm("{ .reg .u64 t; cvta.to.shared.u64 t, %1; cvt.u32.u64 %0, t; }" : "=r"(a) : "l"(p));
    return a;
}
__device__ __forceinline__ uint32_t cvt_tf32(float f) {
    uint32_t u;
    asm("cvt.rn.tf32.f32 %0, %1;" : "=r"(u) : "f"(f));
    return u;
}
#define CP16(dst, src) \
    asm volatile("cp.async.cg.shared.global [%0], [%1], 16;" :: "r"(dst), "l"(src) : "memory")
#define CP_COMMIT() asm volatile("cp.async.commit_group;" ::: "memory")
#define CP_WAIT0()  asm volatile("cp.async.wait_group 0;" ::: "memory")
#define CP_WAIT1()  asm volatile("cp.async.wait_group 1;" ::: "memory")

#define MMA_TF32(d, a, bfr) \
    asm volatile("mma.sync.aligned.m16n8k8.row.col.f32.tf32.tf32.f32 " \
        "{%0,%1,%2,%3}, {%4,%5,%6,%7}, {%8,%9}, {%0,%1,%2,%3};" \
        : "+f"((d)[0]), "+f"((d)[1]), "+f"((d)[2]), "+f"((d)[3]) \
        : "r"((a)[0]), "r"((a)[1]), "r"((a)[2]), "r"((a)[3]), \
          "r"((bfr)[0]), "r"((bfr)[1]))

// ---------- f32x2 helpers for scalar kernels ----------
__device__ __forceinline__ void fma2(u64& d, u64 a, u64 b) {
    asm("fma.rn.f32x2 %0, %1, %2, %0;" : "+l"(d) : "l"(a), "l"(b));
}
__device__ __forceinline__ float2 unpack2(u64 v) {
    float2 f;
    asm("mov.b64 {%0, %1}, %2;" : "=f"(f.x), "=f"(f.y) : "l"(v));
    return f;
}
__device__ __forceinline__ u64 lds64(const float* p) {
    return *reinterpret_cast<const u64*>(p);
}

// =====================================================================
// Kernel 0a: bake W1 -> g_W1b[g][co][k] as tf32 (cvt.rn).  g = tap*8+cib.
// =====================================================================
__global__ void __launch_bounds__(256) prep_w1(const float* __restrict__ W1)
{
    int idx = blockIdx.x * 256 + threadIdx.x;     // 392*4096
    int g = idx >> 12, e = idx & 4095;
    int co = e >> 5, k = e & 31;
    int tap = g >> 3, cib = g & 7;
    float wv = W1[((size_t)co * CC + cib * 32 + k) * NT + tap];
    g_W1b[idx] = __uint_as_float(cvt_tf32(wv));
}

// =====================================================================
// Kernel 0b: zero-padded x images. xp0[r][c'] = x[r-6][c'-6];
// xp1[r][c'] = x[r-6][c'-4] (2-col shift for odd-tap 16B alignment).
// =====================================================================
__global__ void __launch_bounds__(256) prep_xpad(const float* __restrict__ x)
{
    int idx = blockIdx.x * 256 + threadIdx.x;
    if (idx >= NPC) return;
    int col = idx % XPR;
    int t = idx / XPR;
    int r = t % XPR;
    int bc = t / XPR;
    int rr = r - 6;
    float v0 = 0.f, v1 = 0.f;
    if ((unsigned)rr < HH) {
        const float* xr = x + (size_t)bc * HW + rr * WW;
        int c0 = col - 6;
        if ((unsigned)c0 < WW) v0 = __ldg(xr + c0);
        int c1 = col - 4;
        if ((unsigned)c1 < WW) v1 = __ldg(xr + c1);
    }
    g_xpad[idx] = v0;
    g_xpad[NPC + idx] = v1;
}

// =====================================================================
// Kernel A: conv1 tf32 mma.sync GEMM, all-cp.async, 3-stage pipeline.
// Grid (98, 3), 256 threads (8 warps). CTA tile 128px x 128co; warp 64x32.
// A: As[k][px] stride 136, filled by guard-free cp.async from g_xpad.
// =====================================================================
#define AST 136
#define A_BYTES (32 * AST * 4)          // 17408
#define BST 36
#define B_BYTES (128 * BST * 4)         // 18432
#define NST 3
#define CONV1_SMEM (NST * (A_BYTES + B_BYTES))   // 107520

__global__ void __launch_bounds__(256, 2) conv1_mma()
{
    extern __shared__ __align__(16) char smem[];
    const uint32_t sb = smem_to_u32(smem);
    const uint32_t sbB = sb + NST * A_BYTES;

    const int tid = threadIdx.x;
    const int wid = tid >> 5, lane = tid & 31;
    const int g8 = lane >> 2, t4 = lane & 3;
    const int m0 = (wid >> 2) * 64;       // M half
    const int n0 = (wid & 3) * 32;        // N quarter

    const int q = blockIdx.y;
    const int gstart = q * 131;
    const int gend = (gstart + 131 > GTOT) ? GTOT : (gstart + 131);
    const int n = gend - gstart;

    // A-copy role: pixel quad (qd) x k-slot (kl, +8 per it)
    const int kl = tid >> 5;
    const int qd = tid & 31;
    const int gp = blockIdx.x * 128 + qd * 4;
    const int b4 = gp / HW, rem4 = gp % HW;
    const int h4 = rem4 / WW, w4 = rem4 % WW;       // w4 multiple of 4
    const float* const aBase = g_xpad + (size_t)(b4 * CC + kl) * XPCH + h4 * XPR + w4;
    const uint32_t a_dst0 = sb + (uint32_t)(kl * AST + qd * 4) * 4;

    auto issue = [&](int g, int s) {
        // ---- B: 16KB tile ----
        const char* srcB = (const char*)(g_W1b + (size_t)g * 4096);
        uint32_t dstb = sbB + (uint32_t)s * B_BYTES;
#pragma unroll
        for (int i2 = 0; i2 < 4; ++i2) {
            int c = tid + i2 * 256;
            int co = c >> 3, kk2 = c & 7;
            CP16(dstb + (uint32_t)(co * BST + kk2 * 4) * 4, srcB + (size_t)c * 16);
        }
        // ---- A: 16KB patch tile, guard-free from padded image ----
        int tap = g >> 3, cib = g & 7;
        int di = tap / 7, dj = tap - di * 7;
        int par = dj & 1;
        const float* sA = aBase + (par ? NPC : 0) + (size_t)(cib * 32) * XPCH
                        + di * (2 * XPR) + (2 * dj - 2 * par);
        uint32_t dA = a_dst0 + (uint32_t)s * A_BYTES;
#pragma unroll
        for (int it = 0; it < 4; ++it) {
            CP16(dA, (const char*)sA);
            dA += 8 * AST * 4;
            sA += (size_t)8 * XPCH;
        }
        CP_COMMIT();
    };

    float acc[4][4][4];
#pragma unroll
    for (int i = 0; i < 4; ++i)
#pragma unroll
        for (int j = 0; j < 4; ++j)
#pragma unroll
            for (int c = 0; c < 4; ++c) acc[i][j][c] = 0.f;

    issue(gstart, 0);
    issue(gstart + 1, 1);

    for (int gi = 0; gi < n; ++gi) {
        const int s = gi % NST;
        if (gi + 1 < n) { CP_WAIT1(); } else { CP_WAIT0(); }
        __syncthreads();

        const float* ap = (const float*)(smem + s * A_BYTES) + m0;
        const float* bp = (const float*)(smem + NST * A_BYTES + s * B_BYTES) + n0 * BST;
#pragma unroll
        for (int kk = 0; kk < 4; ++kk) {
            const int k0 = kk * 8;
            uint32_t af[4][4], bf[4][2];
#pragma unroll
            for (int i = 0; i < 4; ++i) {
                const float* ar = ap + (k0 + t4) * AST + 16 * i + g8;
                af[i][0] = __float_as_uint(ar[0]);
                af[i][1] = __float_as_uint(ar[8]);
                af[i][2] = __float_as_uint(ar[4 * AST]);
                af[i][3] = __float_as_uint(ar[4 * AST + 8]);
            }
#pragma unroll
            for (int j = 0; j < 4; ++j) {
                const float* br = bp + (8 * j + g8) * BST + k0 + t4;
                bf[j][0] = __float_as_uint(br[0]);
                bf[j][1] = __float_as_uint(br[4]);
            }
#pragma unroll
            for (int i = 0; i < 4; ++i)
#pragma unroll
                for (int j = 0; j < 4; ++j)
                    MMA_TF32(acc[i][j], af[i], bf[j]);
        }

        if (gi + 2 < n) issue(gstart + gi + 2, (gi + 2) % NST);
    }
    __syncthreads();

    // ---- epilogue: acc -> smem [co][px] (stride 132) -> coalesced STG ----
    float* const Cs = (float*)smem;
#pragma unroll
    for (int i = 0; i < 4; ++i)
#pragma unroll
        for (int j = 0; j < 4; ++j) {
            int row0 = m0 + 16 * i + g8;
            int col0 = n0 + 8 * j + 2 * t4;
            Cs[(col0)     * 132 + row0]     = acc[i][j][0];
            Cs[(col0 + 1) * 132 + row0]     = acc[i][j][1];
            Cs[(col0)     * 132 + row0 + 8] = acc[i][j][2];
            Cs[(col0 + 1) * 132 + row0 + 8] = acc[i][j][3];
        }
    __syncthreads();

    {
        const int pxl = tid & 127, ch = tid >> 7;
        const int pxg = blockIdx.x * 128 + pxl;
        const int b2 = pxg / HW, rem2 = pxg % HW;
        float* base = g_part + ((size_t)(q * BB + b2) * CO) * HW + rem2;
#pragma unroll 4
        for (int co = ch * 64; co < ch * 64 + 64; ++co)
            base[(size_t)co * HW] = Cs[co * 132 + pxl];
    }
}

// =====================================================================
// Kernel B: thread-per-pixel conv2 (1x1, 128->49) + softmax.
// Grid 98 x 128 threads. W2/b2 staged in smem; logits in registers.
// =====================================================================
__global__ void __launch_bounds__(128) conv2_softmax_kernel(
    const float* __restrict__ W2, const float* __restrict__ b1,
    const float* __restrict__ b2)
{
    __shared__ float W2s[NT * 128];
    __shared__ float b2s[NT];
    __shared__ float b1s[CO];
    const int tid = threadIdx.x;

    for (int t = tid; t < NT * 128; t += 128) W2s[t] = __ldg(&W2[t]);
    if (tid < NT) b2s[tid] = __ldg(&b2[tid]);
    if (tid < CO) b1s[tid] = __ldg(&b1[tid]);
    __syncthreads();

    const int px = blockIdx.x * 128 + tid;
    const int b = px / HW, rem = px % HW;

    float acc[NT];
#pragma unroll
    for (int kk = 0; kk < NT; ++kk) acc[kk] = b2s[kk];

    const float* p0 = g_part + ((size_t)(0 * BB + b) * CO) * HW + rem;
    const float* p1 = g_part + ((size_t)(1 * BB + b) * CO) * HW + rem;
    const float* p2 = g_part + ((size_t)(2 * BB + b) * CO) * HW + rem;

#pragma unroll 4
    for (int c = 0; c < CO; ++c) {
        float kv = p0[(size_t)c * HW] + p1[(size_t)c * HW] + p2[(size_t)c * HW]
                 + b1s[c];
        const float* wc = &W2s[c];
#pragma unroll
        for (int kk = 0; kk < NT; ++kk)
            acc[kk] = fmaf(kv, wc[kk * 128], acc[kk]);
    }

    // softmax over 49 in registers
    float m = acc[0];
#pragma unroll
    for (int kk = 1; kk < NT; ++kk) m = fmaxf(m, acc[kk]);
    float s = 0.f;
#pragma unroll
    for (int kk = 0; kk < NT; ++kk) {
        acc[kk] = expf(acc[kk] - m);
        s += acc[kk];
    }
    float inv = 1.f / s;
    float* dst = g_attn + (size_t)b * NT * HW + rem;
#pragma unroll
    for (int kk = 0; kk < NT; ++kk)
        dst[(size_t)kk * HW] = acc[kk] * inv;
}

// =====================================================================
// Kernel C: weighted local sum over 49 dilated taps -> out
// Grid (56, 4, 2), 224 threads. Thread = 2 channels x 2 px.
// Guard-free float4 tile loads from padded x.
// =====================================================================
__global__ void __launch_bounds__(224) gather_kernel(float* __restrict__ out)
{
    __shared__ __align__(16) float at[49][60];
    __shared__ __align__(16) float xs[112][68];   // [c*7+i][col], c<16
    const int h = blockIdx.x, b = blockIdx.y;
    const int chalf = blockIdx.z * 128;
    const int tid = threadIdx.x;

    // attn tile: float4 loads (rows 16B-aligned in gmem and smem)
    for (int t = tid; t < 49 * 14; t += 224) {
        int kk = t / 14, p4 = t - kk * 14;
        *reinterpret_cast<float4*>(&at[kk][p4 * 4]) =
            *reinterpret_cast<const float4*>(
                g_attn + ((size_t)b * NT + kk) * HW + h * WW + p4 * 4);
    }

    const int pg = tid % 28, cg = tid / 28;   // 28 px-pairs x 8 channel-pairs
    const int p0 = pg * 2;
    const int c0 = cg * 2, c1 = c0 + 1;

    for (int ch = 0; ch < 8; ++ch) {
        __syncthreads();
        // x tile: 16 ch x 7 rows x 68 cols, guard-free from padded image
        const float* xpc = g_xpad + (size_t)(b * CC + chalf + ch * 16) * XPCH
                         + (size_t)h * XPR;
        for (int t = tid; t < 16 * 7 * 17; t += 224) {
            int c = t / 119;
            int r = t - c * 119;
            int i = r / 17;
            int qd = r - i * 17;
            *reinterpret_cast<float4*>(&xs[c * 7 + i][qd * 4]) =
                *reinterpret_cast<const float4*>(xpc + (size_t)c * XPCH
                                                 + i * (2 * XPR) + qd * 4);
        }
        __syncthreads();

        u64 a0 = 0ull, a1 = 0ull;
#pragma unroll
        for (int i = 0; i < 7; ++i) {
            const float* xr0 = &xs[c0 * 7 + i][p0 + 6];
            const float* xr1 = &xs[c1 * 7 + i][p0 + 6];
#pragma unroll
            for (int j = 0; j < 7; ++j) {
                u64 av = lds64(&at[i * 7 + j][p0]);
                fma2(a0, av, lds64(xr0 + 2 * j - 6));
                fma2(a1, av, lds64(xr1 + 2 * j - 6));
            }
        }
        size_t o0 = (size_t)(b * CC + chalf + ch * 16 + c0) * HW + h * WW + p0;
        size_t o1 = (size_t)(b * CC + chalf + ch * 16 + c1) * HW + h * WW + p0;
        *reinterpret_cast<float2*>(&out[o0]) = unpack2(a0);
        *reinterpret_cast<float2*>(&out[o1]) = unpack2(a1);
    }
}

// =====================================================================
extern "C" void kernel_launch(void* const* d_in, const int* in_sizes, int n_in,
                              void* d_out, int out_size)
{
    const float* x  = (const float*)d_in[0];
    const float* W1 = (const float*)d_in[1];
    const float* b1 = (const float*)d_in[2];
    const float* W2 = (const float*)d_in[3];
    const float* b2 = (const float*)d_in[4];
    for (int i = 0; i < n_in; ++i) {
        switch (in_sizes[i]) {
            case BB * CC * HW: x  = (const float*)d_in[i]; break;
            case CO * CC * NT: W1 = (const float*)d_in[i]; break;
            case CO:           b1 = (const float*)d_in[i]; break;
            case NT * CO:      W2 = (const float*)d_in[i]; break;
            case NT:           b2 = (const float*)d_in[i]; break;
            default: break;
        }
    }
    float* out = (float*)d_out;

    cudaFuncSetAttribute(conv1_mma, cudaFuncAttributeMaxDynamicSharedMemorySize,
                         CONV1_SMEM);
    prep_w1<<<6272, 256>>>(W1);
    prep_xpad<<<(NPC + 255) / 256, 256>>>(x);
    conv1_mma<<<dim3(98, KSPL), 256, CONV1_SMEM>>>();
    conv2_softmax_kernel<<<98, 128>>>(W2, b1, b2);
    gather_kernel<<<dim3(56, 4, 2), 224>>>(out);
}